// round 7
// baseline (speedup 1.0000x reference)
#include <cuda_runtime.h>
#include <math.h>

#define NROW 512
#define CZ   128
#define NPAIR (NROW * NROW) /* 262144 */

typedef unsigned int u32;

// ---------------- device scratch ----------------
__device__ float g_A[(size_t)CZ * NPAIR];   // a, [c][i*512 + kperm]
__device__ float g_B[(size_t)CZ * NPAIR];   // b, [c][j*512 + kperm]
__device__ float g_G[(size_t)CZ * NPAIR];   // gate, [c][pair] (natural)
__device__ float g_T[(size_t)CZ * NPAIR];   // t, [c][i*512+j] (natural)
__device__ float g_wt[6 * 128 * 128];       // weights, pair layout [n][128]
// img order: 0 w_ap, 1 w_ag, 2 w_bp, 3 w_bg, 4 w_g, 5 w_z

// ---------------- helpers ----------------
__device__ __forceinline__ float tf32r(float x) {
    float r;
    asm("cvt.rna.tf32.f32 %0, %1;" : "=f"(r) : "f"(x));
    return r;
}
__device__ __forceinline__ float wsum(float v) {
#pragma unroll
    for (int o = 16; o; o >>= 1) v += __shfl_xor_sync(0xffffffffu, v, o);
    return v;
}
__device__ __forceinline__ float sigm(float x) {
    return 1.0f / (1.0f + __expf(-x));
}
__device__ __forceinline__ void mma8(float* d, const u32* a, const u32* b) {
    asm volatile(
        "mma.sync.aligned.m16n8k8.row.col.f32.tf32.tf32.f32 "
        "{%0,%1,%2,%3}, {%4,%5,%6,%7}, {%8,%9}, {%0,%1,%2,%3};"
        : "+f"(d[0]), "+f"(d[1]), "+f"(d[2]), "+f"(d[3])
        : "r"(a[0]), "r"(a[1]), "r"(a[2]), "r"(a[3]), "r"(b[0]), "r"(b[1]));
}
__device__ __forceinline__ u32 smem_u32(const void* p) {
    u32 a;
    asm("{ .reg .u64 t; cvta.to.shared.u64 t, %1; cvt.u32.u64 %0, t; }" : "=r"(a) : "l"(p));
    return a;
}
__device__ __forceinline__ void cpa16(u32 dst, const void* src) {
    asm volatile("cp.async.cg.shared.global [%0], [%1], 16;" :: "r"(dst), "l"(src));
}
#define CP_COMMIT() asm volatile("cp.async.commit_group;" ::: "memory")
#define CP_WAIT(n)  asm volatile("cp.async.wait_group %0;" :: "n"(n) : "memory")

// ============================================================================
// prep: transpose + tf32-round weights into pair layout:
// g_wt[img][n*128 + (k>>3)*8 + (k&3)*2 + ((k&4)>>2)]
// ============================================================================
__global__ void prep_w(const float* __restrict__ wap, const float* __restrict__ wag,
                       const float* __restrict__ wbp, const float* __restrict__ wbg,
                       const float* __restrict__ wg,  const float* __restrict__ wz) {
    int img = blockIdx.y;
    int lin = blockIdx.x * 256 + threadIdx.x;
    int n = lin >> 7, k = lin & 127;
    const float* s;
    switch (img) {
        case 0: s = wap; break; case 1: s = wag; break;
        case 2: s = wbp; break; case 3: s = wbg; break;
        case 4: s = wg;  break; default: s = wz; break;
    }
    int pos = n * 128 + (k >> 3) * 8 + (k & 3) * 2 + ((k & 4) >> 2);
    g_wt[img * 16384 + pos] = tf32r(s[k * 128 + n]);
}

// ============================================================================
// GEMM: warp tile m16 x n64, K=128. A from smem (pair layout, stride 68 f2),
// B fragments straight from gmem weight image (L1/L2 resident) via __ldg.
// ============================================================================
__device__ __forceinline__ void gemm64_ldg(const float2* __restrict__ As2,
                                           const float2* __restrict__ W2,
                                           int cb, int aoff, int g, int t,
                                           float acc[8][4]) {
#pragma unroll
    for (int i = 0; i < 8; ++i)
#pragma unroll
        for (int q = 0; q < 4; ++q) acc[i][q] = 0.f;
#pragma unroll
    for (int ks = 0; ks < 16; ++ks) {
        float2 a0 = As2[aoff + ks * 4];
        float2 a1 = As2[aoff + ks * 4 + 544];   // +8 rows
        u32 aa[4] = { __float_as_uint(a0.x), __float_as_uint(a1.x),
                      __float_as_uint(a0.y), __float_as_uint(a1.y) };
#pragma unroll
        for (int nt = 0; nt < 8; ++nt) {
            float2 b = __ldg(&W2[(size_t)(cb + nt * 8 + g) * 64 + ks * 4 + t]);
            u32 bb[2] = { __float_as_uint(b.x), __float_as_uint(b.y) };
            mma8(acc[nt], aa, bb);
        }
    }
}

// ============================================================================
// proj_all: LN once (single barrier), then 10 barrier-free GEMM+epilogue
// passes. a/b rows stored k-PERMUTED (pp(g)) so tri can straight-copy.
// smem = As(128x136) = 69632B -> 2 CTAs/SM.
// ============================================================================
__global__ __launch_bounds__(256, 2) void proj_all_kernel(
    const float* __restrict__ z,
    const float* __restrict__ lnw, const float* __restrict__ lnb,
    const float* __restrict__ b_ap, const float* __restrict__ b_ag,
    const float* __restrict__ b_bp, const float* __restrict__ b_bg,
    const float* __restrict__ b_g)
{
    extern __shared__ float smf[];
    float* As = smf;                 // 128 x 136
    const int tid = threadIdx.x;
    const int wid = tid >> 5, lane = tid & 31;
    const int g = lane >> 2, t = lane & 3;
    const int m0 = wid * 16;
    const size_t pair0 = (size_t)blockIdx.x * 128;

    // ---- LN -> As (pair layout) ----
    {
        float4 lw = ((const float4*)lnw)[lane];
        float4 lb = ((const float4*)lnb)[lane];
#pragma unroll 2
        for (int r = 0; r < 16; ++r) {
            int row = wid * 16 + r;
            float4 x = ((const float4*)(z + (pair0 + row) * (size_t)CZ))[lane];
            float m = wsum(x.x + x.y + x.z + x.w) * (1.0f / 128.0f);
            float dx = x.x - m, dy = x.y - m, dz = x.z - m, dw = x.w - m;
            float var = wsum(dx * dx + dy * dy + dz * dz + dw * dw) * (1.0f / 128.0f);
            float rs = rsqrtf(var + 1e-5f);
            float* dst = As + row * 136 + (lane >> 1) * 8 + (lane & 1);
            dst[0] = tf32r(dx * rs * lw.x + lb.x);
            dst[2] = tf32r(dy * rs * lw.y + lb.y);
            dst[4] = tf32r(dz * rs * lw.z + lb.z);
            dst[6] = tf32r(dw * rs * lw.w + lb.w);
        }
    }
    __syncthreads();

    const float2* As2 = (const float2*)As;
    const int aoff = (m0 + g) * 68 + t;
    const int r  = m0 + g;                          // natural row (for g_G)
    const int rp = m0 + (g & 3) * 2 + (g >> 2);     // permuted row (for g_A/g_B)

    float accg[8][4], accp[8][4];

    // ---- a then b (k-permuted rows) ----
#pragma unroll 1
    for (int sel = 0; sel < 2; ++sel) {
        const float2* WP = (const float2*)(g_wt + (sel * 2) * 16384);
        const float2* WG = (const float2*)(g_wt + (sel * 2 + 1) * 16384);
        const float* bp = sel ? b_bp : b_ap;
        const float* bg = sel ? b_bg : b_ag;
        float* __restrict__ dst = sel ? g_B : g_A;
#pragma unroll 1
        for (int cb = 0; cb < 128; cb += 64) {
            gemm64_ldg(As2, WG, cb, aoff, g, t, accg);
            gemm64_ldg(As2, WP, cb, aoff, g, t, accp);
#pragma unroll
            for (int nt = 0; nt < 8; ++nt) {
                int c = cb + nt * 8 + 2 * t;
                float2 bpv = *(const float2*)(bp + c);
                float2 bgv = *(const float2*)(bg + c);
                float* d0 = dst + (size_t)c * NPAIR + pair0;
                float* d1 = dst + (size_t)(c + 1) * NPAIR + pair0;
                d0[rp]     = tf32r(sigm(accg[nt][0] + bgv.x) * (accp[nt][0] + bpv.x));
                d1[rp]     = tf32r(sigm(accg[nt][1] + bgv.y) * (accp[nt][1] + bpv.y));
                d0[rp + 8] = tf32r(sigm(accg[nt][2] + bgv.x) * (accp[nt][2] + bpv.x));
                d1[rp + 8] = tf32r(sigm(accg[nt][3] + bgv.y) * (accp[nt][3] + bpv.y));
            }
        }
    }

    // ---- gate g (natural rows) ----
    {
        const float2* WGt = (const float2*)(g_wt + 4 * 16384);
#pragma unroll 1
        for (int cb = 0; cb < 128; cb += 64) {
            gemm64_ldg(As2, WGt, cb, aoff, g, t, accg);
#pragma unroll
            for (int nt = 0; nt < 8; ++nt) {
                int c = cb + nt * 8 + 2 * t;
                float2 bgv = *(const float2*)(b_g + c);
                float* d0 = g_G + (size_t)c * NPAIR + pair0;
                float* d1 = g_G + (size_t)(c + 1) * NPAIR + pair0;
                d0[r]     = sigm(accg[nt][0] + bgv.x);
                d1[r]     = sigm(accg[nt][1] + bgv.y);
                d0[r + 8] = sigm(accg[nt][2] + bgv.x);
                d1[r + 8] = sigm(accg[nt][3] + bgv.y);
            }
        }
    }
}

// ============================================================================
// tri: t[c][i][j] = sum_k a[c][i][k]*b[c][j][k]; 128x128 tile, K chunks of 32,
// cp.async DOUBLE-buffered (gmem is k-pre-permuted -> straight 16B copies).
// smem 2 x (A 128x40 + B 128x40) x4B = 80KB -> 2 CTAs/SM.
// ============================================================================
__global__ __launch_bounds__(256, 2) void tri_kernel()
{
    extern __shared__ float smf[];   // [buf][A 5120 | B 5120] floats
    const int tid = threadIdx.x;
    const int wid = tid >> 5, lane = tid & 31;
    const int g = lane >> 2, t = lane & 3;
    const int m0 = (wid & 3) * 32, n0 = (wid >> 2) * 64;
    const int c  = blockIdx.z;
    const int i0 = blockIdx.y * 128;
    const int j0 = blockIdx.x * 128;
    const float* __restrict__ asrc = g_A + (size_t)c * NPAIR + (size_t)i0 * NROW;
    const float* __restrict__ bsrc = g_B + (size_t)c * NPAIR + (size_t)j0 * NROW;
    const u32 smb = smem_u32(smf);

    // issue cp.asyncs for chunk s into buffer s&1
    auto issue = [&](int s) {
        const int k0 = s * 32;
        const u32 base = smb + (u32)(s & 1) * 10240u * 4u;
#pragma unroll
        for (int it = 0; it < 4; ++it) {
            int lin = it * 256 + tid;      // 0..1023
            int row = lin >> 3, j = lin & 7;
            u32 doff = (u32)(row * 40 + j * 4) * 4u;
            cpa16(base + doff,
                  asrc + (size_t)row * NROW + k0 + j * 4);
            cpa16(base + 5120u * 4u + doff,
                  bsrc + (size_t)row * NROW + k0 + j * 4);
        }
    };

    float acc[2][8][4];
#pragma unroll
    for (int i = 0; i < 2; ++i)
#pragma unroll
        for (int j = 0; j < 8; ++j)
#pragma unroll
            for (int q = 0; q < 4; ++q) acc[i][j][q] = 0.f;

    const int aoff = (m0 + g) * 20 + t;
    int boff[8];
#pragma unroll
    for (int nt = 0; nt < 8; ++nt) boff[nt] = (n0 + nt * 8 + g) * 20 + t;

    issue(0); CP_COMMIT();

#pragma unroll 1
    for (int kc = 0; kc < 16; ++kc) {
        if (kc < 15) { issue(kc + 1); CP_COMMIT(); CP_WAIT(1); }
        else         { CP_WAIT(0); }
        __syncthreads();

        const float2* A2 = (const float2*)(smf + (kc & 1) * 10240);
        const float2* B2 = (const float2*)(smf + (kc & 1) * 10240 + 5120);
#pragma unroll
        for (int ks = 0; ks < 4; ++ks) {
            float2 a00 = A2[aoff + ks * 4];
            float2 a01 = A2[aoff + ks * 4 + 160];   // +8 rows
            float2 a10 = A2[aoff + ks * 4 + 320];   // +16 rows
            float2 a11 = A2[aoff + ks * 4 + 480];   // +24 rows
            u32 aa0[4] = { __float_as_uint(a00.x), __float_as_uint(a01.x),
                           __float_as_uint(a00.y), __float_as_uint(a01.y) };
            u32 aa1[4] = { __float_as_uint(a10.x), __float_as_uint(a11.x),
                           __float_as_uint(a10.y), __float_as_uint(a11.y) };
#pragma unroll
            for (int nt = 0; nt < 8; ++nt) {
                float2 b = B2[boff[nt] + ks * 4];
                u32 bb[2] = { __float_as_uint(b.x), __float_as_uint(b.y) };
                mma8(acc[0][nt], aa0, bb);
                mma8(acc[1][nt], aa1, bb);
            }
        }
        __syncthreads();   // everyone done reading buf before it is re-filled
    }

    float* __restrict__ tdst = g_T + (size_t)c * NPAIR;
#pragma unroll
    for (int mt = 0; mt < 2; ++mt) {
        int r = i0 + m0 + mt * 16 + g;
#pragma unroll
        for (int nt = 0; nt < 8; ++nt) {
            int cl = j0 + n0 + nt * 8 + 2 * t;
            *(float2*)(tdst + (size_t)r * NROW + cl) =
                make_float2(acc[mt][nt][0], acc[mt][nt][1]);
            *(float2*)(tdst + (size_t)(r + 8) * NROW + cl) =
                make_float2(acc[mt][nt][2], acc[mt][nt][3]);
        }
    }
}

// ============================================================================
// final: out[pair][cz] = g * (LN_c(t) @ Wz + bz). 64-pair tiles, grid 4096.
// W via __ldg (L1-resident). smem = As(128x72)+stats = 39424B -> 3 CTAs/SM.
// ============================================================================
__global__ __launch_bounds__(256, 3) void final_kernel(
    const float* __restrict__ lnw, const float* __restrict__ lnb,
    const float* __restrict__ bz, float* __restrict__ out)
{
    extern __shared__ float smf[];
    float* As = smf;                 // [128 c][72 pair] k-major
    float* PS = As + 128 * 72;       // 256
    float* PQ = PS + 256;            // 256
    float* MS = PQ + 256;            // 64
    float* RS = MS + 64;             // 64
    const int tid = threadIdx.x;
    const int wid = tid >> 5, lane = tid & 31;
    const int g = lane >> 2, t = lane & 3;
    const int m0 = (wid & 3) * 16, n0 = (wid >> 2) * 64;
    const int p = tid & 63, ch = tid >> 6;
    const size_t pair0 = (size_t)blockIdx.x * 64;

    // gather t over c + partial stats
    float s = 0.f, qq = 0.f;
#pragma unroll 4
    for (int cc = 0; cc < 32; ++cc) {
        int c = ch * 32 + cc;
        float v = g_T[(size_t)c * NPAIR + pair0 + p];
        As[c * 72 + p] = v;
        s += v; qq += v * v;
    }
    PS[tid] = s; PQ[tid] = qq;
    __syncthreads();
    if (tid < 64) {
        float ss = PS[tid] + PS[tid + 64] + PS[tid + 128] + PS[tid + 192];
        float sq = PQ[tid] + PQ[tid + 64] + PQ[tid + 128] + PQ[tid + 192];
        float m = ss * (1.0f / 128.0f);
        MS[tid] = m;
        RS[tid] = rsqrtf(fmaxf(sq * (1.0f / 128.0f) - m * m, 0.f) + 1e-5f);
    }
    __syncthreads();

    // normalize in place
    {
        float mp = MS[p], rp = RS[p];
#pragma unroll 4
        for (int cc = 0; cc < 32; ++cc) {
            int c = ch * 32 + cc;
            float lw = __ldg(lnw + c), lb = __ldg(lnb + c);
            As[c * 72 + p] = tf32r((As[c * 72 + p] - mp) * rp * lw + lb);
        }
    }
    __syncthreads();

    // GEMM: warp tile m16 x n64, K=128; A k-major [c][72]; B via __ldg
    float acc[8][4];
#pragma unroll
    for (int i = 0; i < 8; ++i)
#pragma unroll
        for (int q = 0; q < 4; ++q) acc[i][q] = 0.f;

    const float2* W2 = (const float2*)(g_wt + 5 * 16384);
#pragma unroll
    for (int ks = 0; ks < 16; ++ks) {
        const int k0 = ks * 8;
        const float* ap = As + (k0 + t) * 72 + m0 + g;
        u32 aa[4] = { __float_as_uint(ap[0]),      __float_as_uint(ap[8]),
                      __float_as_uint(ap[4 * 72]), __float_as_uint(ap[4 * 72 + 8]) };
#pragma unroll
        for (int nt = 0; nt < 8; ++nt) {
            float2 b = __ldg(&W2[(size_t)(n0 + nt * 8 + g) * 64 + ks * 4 + t]);
            u32 bb[2] = { __float_as_uint(b.x), __float_as_uint(b.y) };
            mma8(acc[nt], aa, bb);
        }
    }

    const int r = m0 + g;
#pragma unroll
    for (int nt = 0; nt < 8; ++nt) {
        int c = n0 + nt * 8 + 2 * t;
        float2 bzv = *(const float2*)(bz + c);
        float gv00 = g_G[(size_t)c * NPAIR + pair0 + r];
        float gv01 = g_G[(size_t)(c + 1) * NPAIR + pair0 + r];
        float gv10 = g_G[(size_t)c * NPAIR + pair0 + r + 8];
        float gv11 = g_G[(size_t)(c + 1) * NPAIR + pair0 + r + 8];
        *(float2*)(out + (pair0 + r) * (size_t)CZ + c) =
            make_float2(gv00 * (acc[nt][0] + bzv.x), gv01 * (acc[nt][1] + bzv.y));
        *(float2*)(out + (pair0 + r + 8) * (size_t)CZ + c) =
            make_float2(gv10 * (acc[nt][2] + bzv.x), gv11 * (acc[nt][3] + bzv.y));
    }
}

// ============================================================================
// kernel_launch
// ============================================================================
extern "C" void kernel_launch(void* const* d_in, const int* in_sizes, int n_in,
                              void* d_out, int out_size)
{
    const float* z        = (const float*)d_in[0];
    const float* ln_in_w  = (const float*)d_in[1];
    const float* ln_in_b  = (const float*)d_in[2];
    const float* ln_out_w = (const float*)d_in[3];
    const float* ln_out_b = (const float*)d_in[4];
    const float* w_ap     = (const float*)d_in[5];
    const float* b_ap     = (const float*)d_in[6];
    const float* w_ag     = (const float*)d_in[7];
    const float* b_ag     = (const float*)d_in[8];
    const float* w_bp     = (const float*)d_in[9];
    const float* b_bp     = (const float*)d_in[10];
    const float* w_bg     = (const float*)d_in[11];
    const float* b_bg     = (const float*)d_in[12];
    const float* w_g      = (const float*)d_in[13];
    const float* b_g      = (const float*)d_in[14];
    const float* w_z      = (const float*)d_in[15];
    const float* b_z      = (const float*)d_in[16];
    float* out = (float*)d_out;

    const int PROJ_SMEM = 128 * 136 * 4;                 // 69632
    const int TRI_SMEM  = 2 * 10240 * 4;                 // 81920
    const int FIN_SMEM  = (128 * 72 + 640) * 4;          // 39424

    cudaFuncSetAttribute(proj_all_kernel, cudaFuncAttributeMaxDynamicSharedMemorySize, PROJ_SMEM);
    cudaFuncSetAttribute(tri_kernel,      cudaFuncAttributeMaxDynamicSharedMemorySize, TRI_SMEM);
    cudaFuncSetAttribute(final_kernel,    cudaFuncAttributeMaxDynamicSharedMemorySize, FIN_SMEM);

    dim3 pgrid(64, 6);
    prep_w<<<pgrid, 256>>>(w_ap, w_ag, w_bp, w_bg, w_g, w_z);

    proj_all_kernel<<<NPAIR / 128, 256, PROJ_SMEM>>>(
        z, ln_in_w, ln_in_b, b_ap, b_ag, b_bp, b_bg, b_g);

    dim3 tgrid(4, 4, 128);
    tri_kernel<<<tgrid, 256, TRI_SMEM>>>();

    final_kernel<<<NPAIR / 64, 256, FIN_SMEM>>>(ln_out_w, ln_out_b, b_z, out);
}

// round 8
// speedup vs baseline: 1.4997x; 1.4997x over previous
#include <cuda_runtime.h>
#include <math.h>

#define NROW 512
#define CZ   128
#define NPAIR (NROW * NROW) /* 262144 */

typedef unsigned int u32;

// ---------------- device scratch ----------------
__device__ float g_A[(size_t)CZ * NPAIR];   // a, [c][i*512 + kperm]
__device__ float g_B[(size_t)CZ * NPAIR];   // b, [c][j*512 + kperm]
__device__ float g_G[(size_t)CZ * NPAIR];   // gate, [c][pair] (natural)
__device__ float g_T[(size_t)CZ * NPAIR];   // t, [c][i*512+j] (natural)
__device__ float g_wt[6 * 128 * 128];       // weights, pair layout [n][128]
// img order: 0 w_ap, 1 w_ag, 2 w_bp, 3 w_bg, 4 w_g, 5 w_z

// ---------------- helpers ----------------
__device__ __forceinline__ float tf32r(float x) {
    float r;
    asm("cvt.rna.tf32.f32 %0, %1;" : "=f"(r) : "f"(x));
    return r;
}
__device__ __forceinline__ float wsum(float v) {
#pragma unroll
    for (int o = 16; o; o >>= 1) v += __shfl_xor_sync(0xffffffffu, v, o);
    return v;
}
__device__ __forceinline__ float sigm(float x) {
    return 1.0f / (1.0f + __expf(-x));
}
__device__ __forceinline__ void mma8(float* d, const u32* a, const u32* b) {
    asm volatile(
        "mma.sync.aligned.m16n8k8.row.col.f32.tf32.tf32.f32 "
        "{%0,%1,%2,%3}, {%4,%5,%6,%7}, {%8,%9}, {%0,%1,%2,%3};"
        : "+f"(d[0]), "+f"(d[1]), "+f"(d[2]), "+f"(d[3])
        : "r"(a[0]), "r"(a[1]), "r"(a[2]), "r"(a[3]), "r"(b[0]), "r"(b[1]));
}
__device__ __forceinline__ u32 smem_u32(const void* p) {
    u32 a;
    asm("{ .reg .u64 t; cvta.to.shared.u64 t, %1; cvt.u32.u64 %0, t; }" : "=r"(a) : "l"(p));
    return a;
}
__device__ __forceinline__ void cpa16(u32 dst, const void* src) {
    asm volatile("cp.async.cg.shared.global [%0], [%1], 16;" :: "r"(dst), "l"(src));
}
#define CP_COMMIT() asm volatile("cp.async.commit_group;" ::: "memory")
#define CP_WAIT(n)  asm volatile("cp.async.wait_group %0;" :: "n"(n) : "memory")

// ============================================================================
// prep: transpose + tf32-round weights into pair layout:
// g_wt[img][n*128 + (k>>3)*8 + (k&3)*2 + ((k&4)>>2)]
// ============================================================================
__global__ void prep_w(const float* __restrict__ wap, const float* __restrict__ wag,
                       const float* __restrict__ wbp, const float* __restrict__ wbg,
                       const float* __restrict__ wg,  const float* __restrict__ wz) {
    int img = blockIdx.y;
    int lin = blockIdx.x * 256 + threadIdx.x;
    int n = lin >> 7, k = lin & 127;
    const float* s;
    switch (img) {
        case 0: s = wap; break; case 1: s = wag; break;
        case 2: s = wbp; break; case 3: s = wbg; break;
        case 4: s = wg;  break; default: s = wz; break;
    }
    int pos = n * 128 + (k >> 3) * 8 + (k & 3) * 2 + ((k & 4) >> 2);
    g_wt[img * 16384 + pos] = tf32r(s[k * 128 + n]);
}

// ============================================================================
// load a 64-row weight chunk (rows nb..nb+63 of image img) into Wc
// (row stride 136 floats = 34 float4; data 32 float4/row)
// ============================================================================
__device__ __forceinline__ void loadWc(float* __restrict__ Wc, int img, int nb, int tid) {
    const float4* src = (const float4*)(g_wt + img * 16384);
#pragma unroll
    for (int it = 0; it < 8; ++it) {
        int lin = it * 256 + tid;          // 0..2047
        int row = lin >> 5, q = lin & 31;
        ((float4*)Wc)[row * 34 + q] = src[(nb + row) * 32 + q];
    }
}

// GEMM: warp tile m16 x n32, K=128. As pair layout (stride 68 f2),
// Wc pair layout (64 rows, stride 68 f2). acc[4][4].
__device__ __forceinline__ void gemm32(const float2* __restrict__ As2,
                                       const float2* __restrict__ Wc2,
                                       int aoff, int boff0, float acc[4][4]) {
#pragma unroll
    for (int i = 0; i < 4; ++i)
#pragma unroll
        for (int q = 0; q < 4; ++q) acc[i][q] = 0.f;
#pragma unroll
    for (int ks = 0; ks < 16; ++ks) {
        float2 a0 = As2[aoff + ks * 4];
        float2 a1 = As2[aoff + ks * 4 + 544];   // +8 rows
        u32 aa[4] = { __float_as_uint(a0.x), __float_as_uint(a1.x),
                      __float_as_uint(a0.y), __float_as_uint(a1.y) };
#pragma unroll
        for (int nt = 0; nt < 4; ++nt) {
            float2 b = Wc2[boff0 + nt * 8 * 68 + ks * 4];
            u32 bb[2] = { __float_as_uint(b.x), __float_as_uint(b.y) };
            mma8(acc[nt], aa, bb);
        }
    }
}

// ============================================================================
// proj_all: 64-pair tiles, LN once, 10 GEMM passes with smem-staged 64-row
// weight chunks. smem = As(64x136) + Wc(64x136) = 69632B -> 3 CTAs/SM.
// a/b rows stored k-PERMUTED (rp) so tri can straight-copy via cp.async.
// ============================================================================
__global__ __launch_bounds__(256, 3) void proj_all_kernel(
    const float* __restrict__ z,
    const float* __restrict__ lnw, const float* __restrict__ lnb,
    const float* __restrict__ b_ap, const float* __restrict__ b_ag,
    const float* __restrict__ b_bp, const float* __restrict__ b_bg,
    const float* __restrict__ b_g)
{
    extern __shared__ float smf[];
    float* As = smf;                 // 64 x 136
    float* Wc = smf + 64 * 136;      // 64 x 136
    const int tid = threadIdx.x;
    const int wid = tid >> 5, lane = tid & 31;
    const int g = lane >> 2, t = lane & 3;
    const int m0 = (wid & 3) * 16, n0 = (wid >> 2) * 32;
    const size_t pair0 = (size_t)blockIdx.x * 64;

    // ---- LN -> As (pair layout); warp handles 8 rows ----
    {
        float4 lw = ((const float4*)lnw)[lane];
        float4 lb = ((const float4*)lnb)[lane];
#pragma unroll 2
        for (int r = 0; r < 8; ++r) {
            int row = wid * 8 + r;
            float4 x = ((const float4*)(z + (pair0 + row) * (size_t)CZ))[lane];
            float m = wsum(x.x + x.y + x.z + x.w) * (1.0f / 128.0f);
            float dx = x.x - m, dy = x.y - m, dz = x.z - m, dw = x.w - m;
            float var = wsum(dx * dx + dy * dy + dz * dz + dw * dw) * (1.0f / 128.0f);
            float rs = rsqrtf(var + 1e-5f);
            float* dst = As + row * 136 + (lane >> 1) * 8 + (lane & 1);
            dst[0] = tf32r(dx * rs * lw.x + lb.x);
            dst[2] = tf32r(dy * rs * lw.y + lb.y);
            dst[4] = tf32r(dz * rs * lw.z + lb.z);
            dst[6] = tf32r(dw * rs * lw.w + lb.w);
        }
    }

    const float2* As2 = (const float2*)As;
    const float2* Wc2 = (const float2*)Wc;
    const int aoff = (m0 + g) * 68 + t;
    const int boff0 = (n0 + g) * 68 + t;
    const int r  = m0 + g;                          // natural row (for g_G)
    const int rp = m0 + (g & 3) * 2 + (g >> 2);     // permuted row (for g_A/g_B)

    float accg[4][4], accp[4][4];

    // ---- a then b (k-permuted rows) ----
#pragma unroll 1
    for (int sel = 0; sel < 2; ++sel) {
        const int imgP = sel * 2, imgG = sel * 2 + 1;
        const float* bp = sel ? b_bp : b_ap;
        const float* bg = sel ? b_bg : b_ag;
        float* __restrict__ dst = sel ? g_B : g_A;
#pragma unroll 1
        for (int cb = 0; cb < 128; cb += 64) {
            __syncthreads();
            loadWc(Wc, imgG, cb, tid);
            __syncthreads();
            gemm32(As2, Wc2, aoff, boff0, accg);
            __syncthreads();
            loadWc(Wc, imgP, cb, tid);
            __syncthreads();
            gemm32(As2, Wc2, aoff, boff0, accp);
#pragma unroll
            for (int nt = 0; nt < 4; ++nt) {
                int c = cb + n0 + nt * 8 + 2 * t;
                float2 bpv = *(const float2*)(bp + c);
                float2 bgv = *(const float2*)(bg + c);
                float* d0 = dst + (size_t)c * NPAIR + pair0;
                float* d1 = dst + (size_t)(c + 1) * NPAIR + pair0;
                d0[rp]     = tf32r(sigm(accg[nt][0] + bgv.x) * (accp[nt][0] + bpv.x));
                d1[rp]     = tf32r(sigm(accg[nt][1] + bgv.y) * (accp[nt][1] + bpv.y));
                d0[rp + 8] = tf32r(sigm(accg[nt][2] + bgv.x) * (accp[nt][2] + bpv.x));
                d1[rp + 8] = tf32r(sigm(accg[nt][3] + bgv.y) * (accp[nt][3] + bpv.y));
            }
        }
    }

    // ---- gate g (natural rows) ----
#pragma unroll 1
    for (int cb = 0; cb < 128; cb += 64) {
        __syncthreads();
        loadWc(Wc, 4, cb, tid);
        __syncthreads();
        gemm32(As2, Wc2, aoff, boff0, accg);
#pragma unroll
        for (int nt = 0; nt < 4; ++nt) {
            int c = cb + n0 + nt * 8 + 2 * t;
            float2 bgv = *(const float2*)(b_g + c);
            float* d0 = g_G + (size_t)c * NPAIR + pair0;
            float* d1 = g_G + (size_t)(c + 1) * NPAIR + pair0;
            d0[r]     = sigm(accg[nt][0] + bgv.x);
            d1[r]     = sigm(accg[nt][1] + bgv.y);
            d0[r + 8] = sigm(accg[nt][2] + bgv.x);
            d1[r + 8] = sigm(accg[nt][3] + bgv.y);
        }
    }
}

// ============================================================================
// tri: t[c][i][j] = sum_k a[c][i][k]*b[c][j][k]; 128x128 tile, K chunks of 32,
// cp.async DOUBLE-buffered (gmem is k-pre-permuted -> straight 16B copies).
// smem 2 x (A 128x40 + B 128x40) x4B = 80KB -> 2 CTAs/SM.
// ============================================================================
__global__ __launch_bounds__(256, 2) void tri_kernel()
{
    extern __shared__ float smf[];   // [buf][A 5120 | B 5120] floats
    const int tid = threadIdx.x;
    const int wid = tid >> 5, lane = tid & 31;
    const int g = lane >> 2, t = lane & 3;
    const int m0 = (wid & 3) * 32, n0 = (wid >> 2) * 64;
    const int c  = blockIdx.z;
    const int i0 = blockIdx.y * 128;
    const int j0 = blockIdx.x * 128;
    const float* __restrict__ asrc = g_A + (size_t)c * NPAIR + (size_t)i0 * NROW;
    const float* __restrict__ bsrc = g_B + (size_t)c * NPAIR + (size_t)j0 * NROW;
    const u32 smb = smem_u32(smf);

    auto issue = [&](int s) {
        const int k0 = s * 32;
        const u32 base = smb + (u32)(s & 1) * 10240u * 4u;
#pragma unroll
        for (int it = 0; it < 4; ++it) {
            int lin = it * 256 + tid;      // 0..1023
            int row = lin >> 3, j = lin & 7;
            u32 doff = (u32)(row * 40 + j * 4) * 4u;
            cpa16(base + doff, asrc + (size_t)row * NROW + k0 + j * 4);
            cpa16(base + 5120u * 4u + doff, bsrc + (size_t)row * NROW + k0 + j * 4);
        }
    };

    float acc[2][8][4];
#pragma unroll
    for (int i = 0; i < 2; ++i)
#pragma unroll
        for (int j = 0; j < 8; ++j)
#pragma unroll
            for (int q = 0; q < 4; ++q) acc[i][j][q] = 0.f;

    const int aoff = (m0 + g) * 20 + t;
    int boff[8];
#pragma unroll
    for (int nt = 0; nt < 8; ++nt) boff[nt] = (n0 + nt * 8 + g) * 20 + t;

    issue(0); CP_COMMIT();

#pragma unroll 1
    for (int kc = 0; kc < 16; ++kc) {
        if (kc < 15) { issue(kc + 1); CP_COMMIT(); CP_WAIT(1); }
        else         { CP_WAIT(0); }
        __syncthreads();

        const float2* A2 = (const float2*)(smf + (kc & 1) * 10240);
        const float2* B2 = (const float2*)(smf + (kc & 1) * 10240 + 5120);
#pragma unroll
        for (int ks = 0; ks < 4; ++ks) {
            float2 a00 = A2[aoff + ks * 4];
            float2 a01 = A2[aoff + ks * 4 + 160];
            float2 a10 = A2[aoff + ks * 4 + 320];
            float2 a11 = A2[aoff + ks * 4 + 480];
            u32 aa0[4] = { __float_as_uint(a00.x), __float_as_uint(a01.x),
                           __float_as_uint(a00.y), __float_as_uint(a01.y) };
            u32 aa1[4] = { __float_as_uint(a10.x), __float_as_uint(a11.x),
                           __float_as_uint(a10.y), __float_as_uint(a11.y) };
#pragma unroll
            for (int nt = 0; nt < 8; ++nt) {
                float2 b = B2[boff[nt] + ks * 4];
                u32 bb[2] = { __float_as_uint(b.x), __float_as_uint(b.y) };
                mma8(acc[0][nt], aa0, bb);
                mma8(acc[1][nt], aa1, bb);
            }
        }
        __syncthreads();
    }

    float* __restrict__ tdst = g_T + (size_t)c * NPAIR;
#pragma unroll
    for (int mt = 0; mt < 2; ++mt) {
        int r = i0 + m0 + mt * 16 + g;
#pragma unroll
        for (int nt = 0; nt < 8; ++nt) {
            int cl = j0 + n0 + nt * 8 + 2 * t;
            *(float2*)(tdst + (size_t)r * NROW + cl) =
                make_float2(acc[mt][nt][0], acc[mt][nt][1]);
            *(float2*)(tdst + (size_t)(r + 8) * NROW + cl) =
                make_float2(acc[mt][nt][2], acc[mt][nt][3]);
        }
    }
}

// ============================================================================
// final: out[pair][cz] = g * (LN_c(t) @ Wz + bz). 64-pair tiles, grid 4096.
// W staged in smem in two 64-row chunks.
// smem = As(128x72) + Wc(64x136) + stats = 74240B -> 3 CTAs/SM.
// ============================================================================
__global__ __launch_bounds__(256, 3) void final_kernel(
    const float* __restrict__ lnw, const float* __restrict__ lnb,
    const float* __restrict__ bz, float* __restrict__ out)
{
    extern __shared__ float smf[];
    float* As = smf;                 // [128 c][72 pair] k-major
    float* Wc = As + 128 * 72;       // 64 x 136
    float* PS = Wc + 64 * 136;       // 256
    float* PQ = PS + 256;            // 256
    float* MS = PQ + 256;            // 64
    float* RS = MS + 64;             // 64
    const int tid = threadIdx.x;
    const int wid = tid >> 5, lane = tid & 31;
    const int g = lane >> 2, t = lane & 3;
    const int m0 = (wid & 3) * 16, n0 = (wid >> 2) * 32;
    const int p = tid & 63, ch = tid >> 6;
    const size_t pair0 = (size_t)blockIdx.x * 64;

    // gather t over c + partial stats
    float s = 0.f, qq = 0.f;
#pragma unroll 4
    for (int cc = 0; cc < 32; ++cc) {
        int c = ch * 32 + cc;
        float v = g_T[(size_t)c * NPAIR + pair0 + p];
        As[c * 72 + p] = v;
        s += v; qq += v * v;
    }
    PS[tid] = s; PQ[tid] = qq;
    __syncthreads();
    if (tid < 64) {
        float ss = PS[tid] + PS[tid + 64] + PS[tid + 128] + PS[tid + 192];
        float sq = PQ[tid] + PQ[tid + 64] + PQ[tid + 128] + PQ[tid + 192];
        float m = ss * (1.0f / 128.0f);
        MS[tid] = m;
        RS[tid] = rsqrtf(fmaxf(sq * (1.0f / 128.0f) - m * m, 0.f) + 1e-5f);
    }
    __syncthreads();

    // normalize in place
    {
        float mp = MS[p], rp = RS[p];
#pragma unroll 4
        for (int cc = 0; cc < 32; ++cc) {
            int c = ch * 32 + cc;
            float lw = __ldg(lnw + c), lb = __ldg(lnb + c);
            As[c * 72 + p] = tf32r((As[c * 72 + p] - mp) * rp * lw + lb);
        }
    }

    const float2* Wc2 = (const float2*)Wc;
    const int boff0 = (n0 + g) * 68 + t;
    const int r = m0 + g;

    // two 64-col chunks of Wz
#pragma unroll 1
    for (int cb = 0; cb < 128; cb += 64) {
        __syncthreads();
        loadWc(Wc, 5, cb, tid);
        __syncthreads();

        float acc[4][4];
#pragma unroll
        for (int i = 0; i < 4; ++i)
#pragma unroll
            for (int q = 0; q < 4; ++q) acc[i][q] = 0.f;

#pragma unroll
        for (int ks = 0; ks < 16; ++ks) {
            const int k0 = ks * 8;
            const float* ap = As + (k0 + t) * 72 + m0 + g;
            u32 aa[4] = { __float_as_uint(ap[0]),      __float_as_uint(ap[8]),
                          __float_as_uint(ap[4 * 72]), __float_as_uint(ap[4 * 72 + 8]) };
#pragma unroll
            for (int nt = 0; nt < 4; ++nt) {
                float2 b = Wc2[boff0 + nt * 8 * 68 + ks * 4];
                u32 bb[2] = { __float_as_uint(b.x), __float_as_uint(b.y) };
                mma8(acc[nt], aa, bb);
            }
        }

#pragma unroll
        for (int nt = 0; nt < 4; ++nt) {
            int c = cb + n0 + nt * 8 + 2 * t;
            float2 bzv = *(const float2*)(bz + c);
            float gv00 = g_G[(size_t)c * NPAIR + pair0 + r];
            float gv01 = g_G[(size_t)(c + 1) * NPAIR + pair0 + r];
            float gv10 = g_G[(size_t)c * NPAIR + pair0 + r + 8];
            float gv11 = g_G[(size_t)(c + 1) * NPAIR + pair0 + r + 8];
            *(float2*)(out + (pair0 + r) * (size_t)CZ + c) =
                make_float2(gv00 * (acc[nt][0] + bzv.x), gv01 * (acc[nt][1] + bzv.y));
            *(float2*)(out + (pair0 + r + 8) * (size_t)CZ + c) =
                make_float2(gv10 * (acc[nt][2] + bzv.x), gv11 * (acc[nt][3] + bzv.y));
        }
    }
}

// ============================================================================
// kernel_launch
// ============================================================================
extern "C" void kernel_launch(void* const* d_in, const int* in_sizes, int n_in,
                              void* d_out, int out_size)
{
    const float* z        = (const float*)d_in[0];
    const float* ln_in_w  = (const float*)d_in[1];
    const float* ln_in_b  = (const float*)d_in[2];
    const float* ln_out_w = (const float*)d_in[3];
    const float* ln_out_b = (const float*)d_in[4];
    const float* w_ap     = (const float*)d_in[5];
    const float* b_ap     = (const float*)d_in[6];
    const float* w_ag     = (const float*)d_in[7];
    const float* b_ag     = (const float*)d_in[8];
    const float* w_bp     = (const float*)d_in[9];
    const float* b_bp     = (const float*)d_in[10];
    const float* w_bg     = (const float*)d_in[11];
    const float* b_bg     = (const float*)d_in[12];
    const float* w_g      = (const float*)d_in[13];
    const float* b_g      = (const float*)d_in[14];
    const float* w_z      = (const float*)d_in[15];
    const float* b_z      = (const float*)d_in[16];
    float* out = (float*)d_out;

    const int PROJ_SMEM = 2 * 64 * 136 * 4;                    // 69632
    const int TRI_SMEM  = 2 * 10240 * 4;                       // 81920
    const int FIN_SMEM  = (128 * 72 + 64 * 136 + 640) * 4;     // 74240

    cudaFuncSetAttribute(proj_all_kernel, cudaFuncAttributeMaxDynamicSharedMemorySize, PROJ_SMEM);
    cudaFuncSetAttribute(tri_kernel,      cudaFuncAttributeMaxDynamicSharedMemorySize, TRI_SMEM);
    cudaFuncSetAttribute(final_kernel,    cudaFuncAttributeMaxDynamicSharedMemorySize, FIN_SMEM);

    dim3 pgrid(64, 6);
    prep_w<<<pgrid, 256>>>(w_ap, w_ag, w_bp, w_bg, w_g, w_z);

    proj_all_kernel<<<NPAIR / 64, 256, PROJ_SMEM>>>(
        z, ln_in_w, ln_in_b, b_ap, b_ag, b_bp, b_bg, b_g);

    dim3 tgrid(4, 4, 128);
    tri_kernel<<<tgrid, 256, TRI_SMEM>>>();

    final_kernel<<<NPAIR / 64, 256, FIN_SMEM>>>(ln_out_w, ln_out_b, b_z, out);
}

// round 9
// speedup vs baseline: 1.5847x; 1.0567x over previous
#include <cuda_runtime.h>
#include <math.h>

#define NROW 512
#define CZ   128
#define NPAIR (NROW * NROW) /* 262144 */

typedef unsigned int u32;

// ---------------- device scratch ----------------
__device__ float g_A[(size_t)CZ * NPAIR];   // a, [c][i*512 + kperm]
__device__ float g_B[(size_t)CZ * NPAIR];   // b, [c][j*512 + kperm]
__device__ float g_G[(size_t)NPAIR * CZ];   // gate, [pair][cz]  (NATURAL)
__device__ float g_T[(size_t)CZ * NPAIR];   // t, [c][i*512+j]
__device__ float g_wt[6 * 128 * 128];       // weights, pair layout [n][128]
// img order: 0 w_ap, 1 w_ag, 2 w_bp, 3 w_bg, 4 w_g, 5 w_z

// ---------------- helpers ----------------
__device__ __forceinline__ float tf32r(float x) {
    float r;
    asm("cvt.rna.tf32.f32 %0, %1;" : "=f"(r) : "f"(x));
    return r;
}
__device__ __forceinline__ float wsum(float v) {
#pragma unroll
    for (int o = 16; o; o >>= 1) v += __shfl_xor_sync(0xffffffffu, v, o);
    return v;
}
__device__ __forceinline__ float sigm(float x) {
    return 1.0f / (1.0f + __expf(-x));
}
__device__ __forceinline__ void mma8(float* d, const u32* a, const u32* b) {
    asm volatile(
        "mma.sync.aligned.m16n8k8.row.col.f32.tf32.tf32.f32 "
        "{%0,%1,%2,%3}, {%4,%5,%6,%7}, {%8,%9}, {%0,%1,%2,%3};"
        : "+f"(d[0]), "+f"(d[1]), "+f"(d[2]), "+f"(d[3])
        : "r"(a[0]), "r"(a[1]), "r"(a[2]), "r"(a[3]), "r"(b[0]), "r"(b[1]));
}
__device__ __forceinline__ u32 smem_u32(const void* p) {
    u32 a;
    asm("{ .reg .u64 t; cvta.to.shared.u64 t, %1; cvt.u32.u64 %0, t; }" : "=r"(a) : "l"(p));
    return a;
}
__device__ __forceinline__ void cpa16(u32 dst, const void* src) {
    asm volatile("cp.async.cg.shared.global [%0], [%1], 16;" :: "r"(dst), "l"(src));
}
#define CP_COMMIT() asm volatile("cp.async.commit_group;" ::: "memory")
#define CP_WAIT(n)  asm volatile("cp.async.wait_group %0;" :: "n"(n) : "memory")

// ============================================================================
// prep: transpose + tf32-round weights into pair layout:
// g_wt[img][n*128 + (k>>3)*8 + (k&3)*2 + ((k&4)>>2)]
// ============================================================================
__global__ void prep_w(const float* __restrict__ wap, const float* __restrict__ wag,
                       const float* __restrict__ wbp, const float* __restrict__ wbg,
                       const float* __restrict__ wg,  const float* __restrict__ wz) {
    int img = blockIdx.y;
    int lin = blockIdx.x * 256 + threadIdx.x;
    int n = lin >> 7, k = lin & 127;
    const float* s;
    switch (img) {
        case 0: s = wap; break; case 1: s = wag; break;
        case 2: s = wbp; break; case 3: s = wbg; break;
        case 4: s = wg;  break; default: s = wz; break;
    }
    int pos = n * 128 + (k >> 3) * 8 + (k & 3) * 2 + ((k & 4) >> 2);
    g_wt[img * 16384 + pos] = tf32r(s[k * 128 + n]);
}

// ============================================================================
// load a 64-row weight chunk (rows nb..nb+63 of image img) into Wc
// ============================================================================
__device__ __forceinline__ void loadWc(float* __restrict__ Wc, int img, int nb, int tid) {
    const float4* src = (const float4*)(g_wt + img * 16384);
#pragma unroll
    for (int it = 0; it < 8; ++it) {
        int lin = it * 256 + tid;          // 0..2047
        int row = lin >> 5, q = lin & 31;
        ((float4*)Wc)[row * 34 + q] = src[(nb + row) * 32 + q];
    }
}

// GEMM: warp tile m16 x n32, K=128. As pair layout (stride 68 f2),
// Wc pair layout (64 rows, stride 68 f2). acc[4][4].
__device__ __forceinline__ void gemm32(const float2* __restrict__ As2,
                                       const float2* __restrict__ Wc2,
                                       int aoff, int boff0, float acc[4][4]) {
#pragma unroll
    for (int i = 0; i < 4; ++i)
#pragma unroll
        for (int q = 0; q < 4; ++q) acc[i][q] = 0.f;
#pragma unroll
    for (int ks = 0; ks < 16; ++ks) {
        float2 a0 = As2[aoff + ks * 4];
        float2 a1 = As2[aoff + ks * 4 + 544];   // +8 rows
        u32 aa[4] = { __float_as_uint(a0.x), __float_as_uint(a1.x),
                      __float_as_uint(a0.y), __float_as_uint(a1.y) };
#pragma unroll
        for (int nt = 0; nt < 4; ++nt) {
            float2 b = Wc2[boff0 + nt * 8 * 68 + ks * 4];
            u32 bb[2] = { __float_as_uint(b.x), __float_as_uint(b.y) };
            mma8(acc[nt], aa, bb);
        }
    }
}

// ============================================================================
// proj_all: 64-pair tiles, LN once, 10 GEMM passes with smem-staged 64-row
// weight chunks. smem = As(64x136) + Wc(64x136) = 69632B -> 3 CTAs/SM.
// ============================================================================
__global__ __launch_bounds__(256, 3) void proj_all_kernel(
    const float* __restrict__ z,
    const float* __restrict__ lnw, const float* __restrict__ lnb,
    const float* __restrict__ b_ap, const float* __restrict__ b_ag,
    const float* __restrict__ b_bp, const float* __restrict__ b_bg,
    const float* __restrict__ b_g)
{
    extern __shared__ float smf[];
    float* As = smf;                 // 64 x 136
    float* Wc = smf + 64 * 136;      // 64 x 136
    const int tid = threadIdx.x;
    const int wid = tid >> 5, lane = tid & 31;
    const int g = lane >> 2, t = lane & 3;
    const int m0 = (wid & 3) * 16, n0 = (wid >> 2) * 32;
    const size_t pair0 = (size_t)blockIdx.x * 64;

    // ---- LN -> As (pair layout); warp handles 8 rows ----
    {
        float4 lw = ((const float4*)lnw)[lane];
        float4 lb = ((const float4*)lnb)[lane];
#pragma unroll 2
        for (int r = 0; r < 8; ++r) {
            int row = wid * 8 + r;
            float4 x = ((const float4*)(z + (pair0 + row) * (size_t)CZ))[lane];
            float m = wsum(x.x + x.y + x.z + x.w) * (1.0f / 128.0f);
            float dx = x.x - m, dy = x.y - m, dz = x.z - m, dw = x.w - m;
            float var = wsum(dx * dx + dy * dy + dz * dz + dw * dw) * (1.0f / 128.0f);
            float rs = rsqrtf(var + 1e-5f);
            float* dst = As + row * 136 + (lane >> 1) * 8 + (lane & 1);
            dst[0] = tf32r(dx * rs * lw.x + lb.x);
            dst[2] = tf32r(dy * rs * lw.y + lb.y);
            dst[4] = tf32r(dz * rs * lw.z + lb.z);
            dst[6] = tf32r(dw * rs * lw.w + lb.w);
        }
    }

    const float2* As2 = (const float2*)As;
    const float2* Wc2 = (const float2*)Wc;
    const int aoff = (m0 + g) * 68 + t;
    const int boff0 = (n0 + g) * 68 + t;
    const int r  = m0 + g;                          // natural row
    const int rp = m0 + (g & 3) * 2 + (g >> 2);     // permuted row (for g_A/g_B)

    float accg[4][4], accp[4][4];

    // ---- a then b (k-permuted rows) ----
#pragma unroll 1
    for (int sel = 0; sel < 2; ++sel) {
        const int imgP = sel * 2, imgG = sel * 2 + 1;
        const float* bp = sel ? b_bp : b_ap;
        const float* bg = sel ? b_bg : b_ag;
        float* __restrict__ dst = sel ? g_B : g_A;
#pragma unroll 1
        for (int cb = 0; cb < 128; cb += 64) {
            __syncthreads();
            loadWc(Wc, imgG, cb, tid);
            __syncthreads();
            gemm32(As2, Wc2, aoff, boff0, accg);
            __syncthreads();
            loadWc(Wc, imgP, cb, tid);
            __syncthreads();
            gemm32(As2, Wc2, aoff, boff0, accp);
#pragma unroll
            for (int nt = 0; nt < 4; ++nt) {
                int c = cb + n0 + nt * 8 + 2 * t;
                float2 bpv = *(const float2*)(bp + c);
                float2 bgv = *(const float2*)(bg + c);
                float* d0 = dst + (size_t)c * NPAIR + pair0;
                float* d1 = dst + (size_t)(c + 1) * NPAIR + pair0;
                d0[rp]     = tf32r(sigm(accg[nt][0] + bgv.x) * (accp[nt][0] + bpv.x));
                d1[rp]     = tf32r(sigm(accg[nt][1] + bgv.y) * (accp[nt][1] + bpv.y));
                d0[rp + 8] = tf32r(sigm(accg[nt][2] + bgv.x) * (accp[nt][2] + bpv.x));
                d1[rp + 8] = tf32r(sigm(accg[nt][3] + bgv.y) * (accp[nt][3] + bpv.y));
            }
        }
    }

    // ---- gate g: NATURAL [pair][cz] layout, float2 stores ----
#pragma unroll 1
    for (int cb = 0; cb < 128; cb += 64) {
        __syncthreads();
        loadWc(Wc, 4, cb, tid);
        __syncthreads();
        gemm32(As2, Wc2, aoff, boff0, accg);
#pragma unroll
        for (int nt = 0; nt < 4; ++nt) {
            int c = cb + n0 + nt * 8 + 2 * t;
            float2 bgv = *(const float2*)(b_g + c);
            *(float2*)(g_G + (pair0 + r) * (size_t)CZ + c) =
                make_float2(sigm(accg[nt][0] + bgv.x), sigm(accg[nt][1] + bgv.y));
            *(float2*)(g_G + (pair0 + r + 8) * (size_t)CZ + c) =
                make_float2(sigm(accg[nt][2] + bgv.x), sigm(accg[nt][3] + bgv.y));
        }
    }
}

// ============================================================================
// tri: t[c][i][j] = sum_k a[c][i][k]*b[c][j][k]; 128x128 tile, K chunks of 32,
// cp.async DOUBLE-buffered. smem 80KB -> 2 CTAs/SM.
// ============================================================================
__global__ __launch_bounds__(256, 2) void tri_kernel()
{
    extern __shared__ float smf[];   // [buf][A 5120 | B 5120] floats
    const int tid = threadIdx.x;
    const int wid = tid >> 5, lane = tid & 31;
    const int g = lane >> 2, t = lane & 3;
    const int m0 = (wid & 3) * 32, n0 = (wid >> 2) * 64;
    const int c  = blockIdx.z;
    const int i0 = blockIdx.y * 128;
    const int j0 = blockIdx.x * 128;
    const float* __restrict__ asrc = g_A + (size_t)c * NPAIR + (size_t)i0 * NROW;
    const float* __restrict__ bsrc = g_B + (size_t)c * NPAIR + (size_t)j0 * NROW;
    const u32 smb = smem_u32(smf);

    auto issue = [&](int s) {
        const int k0 = s * 32;
        const u32 base = smb + (u32)(s & 1) * 10240u * 4u;
#pragma unroll
        for (int it = 0; it < 4; ++it) {
            int lin = it * 256 + tid;      // 0..1023
            int row = lin >> 3, j = lin & 7;
            u32 doff = (u32)(row * 40 + j * 4) * 4u;
            cpa16(base + doff, asrc + (size_t)row * NROW + k0 + j * 4);
            cpa16(base + 5120u * 4u + doff, bsrc + (size_t)row * NROW + k0 + j * 4);
        }
    };

    float acc[2][8][4];
#pragma unroll
    for (int i = 0; i < 2; ++i)
#pragma unroll
        for (int j = 0; j < 8; ++j)
#pragma unroll
            for (int q = 0; q < 4; ++q) acc[i][j][q] = 0.f;

    const int aoff = (m0 + g) * 20 + t;
    int boff[8];
#pragma unroll
    for (int nt = 0; nt < 8; ++nt) boff[nt] = (n0 + nt * 8 + g) * 20 + t;

    issue(0); CP_COMMIT();

#pragma unroll 1
    for (int kc = 0; kc < 16; ++kc) {
        if (kc < 15) { issue(kc + 1); CP_COMMIT(); CP_WAIT(1); }
        else         { CP_WAIT(0); }
        __syncthreads();

        const float2* A2 = (const float2*)(smf + (kc & 1) * 10240);
        const float2* B2 = (const float2*)(smf + (kc & 1) * 10240 + 5120);
#pragma unroll
        for (int ks = 0; ks < 4; ++ks) {
            float2 a00 = A2[aoff + ks * 4];
            float2 a01 = A2[aoff + ks * 4 + 160];
            float2 a10 = A2[aoff + ks * 4 + 320];
            float2 a11 = A2[aoff + ks * 4 + 480];
            u32 aa0[4] = { __float_as_uint(a00.x), __float_as_uint(a01.x),
                           __float_as_uint(a00.y), __float_as_uint(a01.y) };
            u32 aa1[4] = { __float_as_uint(a10.x), __float_as_uint(a11.x),
                           __float_as_uint(a10.y), __float_as_uint(a11.y) };
#pragma unroll
            for (int nt = 0; nt < 8; ++nt) {
                float2 b = B2[boff[nt] + ks * 4];
                u32 bb[2] = { __float_as_uint(b.x), __float_as_uint(b.y) };
                mma8(acc[0][nt], aa0, bb);
                mma8(acc[1][nt], aa1, bb);
            }
        }
        __syncthreads();
    }

    float* __restrict__ tdst = g_T + (size_t)c * NPAIR;
#pragma unroll
    for (int mt = 0; mt < 2; ++mt) {
        int r = i0 + m0 + mt * 16 + g;
#pragma unroll
        for (int nt = 0; nt < 8; ++nt) {
            int cl = j0 + n0 + nt * 8 + 2 * t;
            *(float2*)(tdst + (size_t)r * NROW + cl) =
                make_float2(acc[mt][nt][0], acc[mt][nt][1]);
            *(float2*)(tdst + (size_t)(r + 8) * NROW + cl) =
                make_float2(acc[mt][nt][2], acc[mt][nt][3]);
        }
    }
}

// ============================================================================
// final: out[pair][cz] = g * (LN_c(t) @ Wz + bz). 64-pair tiles, grid 4096.
// t gathered via cp.async; gate in natural layout (coalesced with out).
// smem = As(128x72) + Wc(64x136) + stats = 74240B -> 3 CTAs/SM.
// ============================================================================
__global__ __launch_bounds__(256, 3) void final_kernel(
    const float* __restrict__ lnw, const float* __restrict__ lnb,
    const float* __restrict__ bz, float* __restrict__ out)
{
    extern __shared__ float smf[];
    float* As = smf;                 // [128 c][72 pair] k-major
    float* Wc = As + 128 * 72;       // 64 x 136
    float* PS = Wc + 64 * 136;       // 256
    float* PQ = PS + 256;            // 256
    float* MS = PQ + 256;            // 64
    float* RS = MS + 64;             // 64
    const int tid = threadIdx.x;
    const int wid = tid >> 5, lane = tid & 31;
    const int g = lane >> 2, t = lane & 3;
    const int m0 = (wid & 3) * 16, n0 = (wid >> 2) * 32;
    const int p = tid & 63, ch = tid >> 6;
    const size_t pair0 = (size_t)blockIdx.x * 64;
    const u32 smb = smem_u32(smf);

    // ---- async gather of t: 2048 x 16B, 8 per thread ----
#pragma unroll
    for (int it = 0; it < 8; ++it) {
        int lin = it * 256 + tid;        // 0..2047
        int c = lin >> 4, p4 = lin & 15;
        cpa16(smb + (u32)(c * 72 + p4 * 4) * 4u,
              g_T + (size_t)c * NPAIR + pair0 + p4 * 4);
    }
    CP_COMMIT();
    CP_WAIT(0);
    __syncthreads();

    // ---- stats from smem ----
    {
        float s = 0.f, qq = 0.f;
#pragma unroll 4
        for (int cc = 0; cc < 32; ++cc) {
            int c = ch * 32 + cc;
            float v = As[c * 72 + p];
            s += v; qq += v * v;
        }
        PS[tid] = s; PQ[tid] = qq;
    }
    __syncthreads();
    if (tid < 64) {
        float ss = PS[tid] + PS[tid + 64] + PS[tid + 128] + PS[tid + 192];
        float sq = PQ[tid] + PQ[tid + 64] + PQ[tid + 128] + PQ[tid + 192];
        float m = ss * (1.0f / 128.0f);
        MS[tid] = m;
        RS[tid] = rsqrtf(fmaxf(sq * (1.0f / 128.0f) - m * m, 0.f) + 1e-5f);
    }
    __syncthreads();

    // normalize in place
    {
        float mp = MS[p], rp = RS[p];
#pragma unroll 4
        for (int cc = 0; cc < 32; ++cc) {
            int c = ch * 32 + cc;
            float lw = __ldg(lnw + c), lb = __ldg(lnb + c);
            As[c * 72 + p] = tf32r((As[c * 72 + p] - mp) * rp * lw + lb);
        }
    }

    const float2* Wc2 = (const float2*)Wc;
    const int boff0 = (n0 + g) * 68 + t;
    const int r = m0 + g;

    // two 64-col chunks of Wz
#pragma unroll 1
    for (int cb = 0; cb < 128; cb += 64) {
        __syncthreads();
        loadWc(Wc, 5, cb, tid);
        __syncthreads();

        float acc[4][4];
#pragma unroll
        for (int i = 0; i < 4; ++i)
#pragma unroll
            for (int q = 0; q < 4; ++q) acc[i][q] = 0.f;

#pragma unroll
        for (int ks = 0; ks < 16; ++ks) {
            const int k0 = ks * 8;
            const float* ap = As + (k0 + t) * 72 + m0 + g;
            u32 aa[4] = { __float_as_uint(ap[0]),      __float_as_uint(ap[8]),
                          __float_as_uint(ap[4 * 72]), __float_as_uint(ap[4 * 72 + 8]) };
#pragma unroll
            for (int nt = 0; nt < 4; ++nt) {
                float2 b = Wc2[boff0 + nt * 8 * 68 + ks * 4];
                u32 bb[2] = { __float_as_uint(b.x), __float_as_uint(b.y) };
                mma8(acc[nt], aa, bb);
            }
        }

#pragma unroll
        for (int nt = 0; nt < 4; ++nt) {
            int c = cb + n0 + nt * 8 + 2 * t;
            float2 bzv = *(const float2*)(bz + c);
            float2 gv0 = *(const float2*)(g_G + (pair0 + r) * (size_t)CZ + c);
            float2 gv1 = *(const float2*)(g_G + (pair0 + r + 8) * (size_t)CZ + c);
            *(float2*)(out + (pair0 + r) * (size_t)CZ + c) =
                make_float2(gv0.x * (acc[nt][0] + bzv.x), gv0.y * (acc[nt][1] + bzv.y));
            *(float2*)(out + (pair0 + r + 8) * (size_t)CZ + c) =
                make_float2(gv1.x * (acc[nt][2] + bzv.x), gv1.y * (acc[nt][3] + bzv.y));
        }
    }
}

// ============================================================================
// kernel_launch
// ============================================================================
extern "C" void kernel_launch(void* const* d_in, const int* in_sizes, int n_in,
                              void* d_out, int out_size)
{
    const float* z        = (const float*)d_in[0];
    const float* ln_in_w  = (const float*)d_in[1];
    const float* ln_in_b  = (const float*)d_in[2];
    const float* ln_out_w = (const float*)d_in[3];
    const float* ln_out_b = (const float*)d_in[4];
    const float* w_ap     = (const float*)d_in[5];
    const float* b_ap     = (const float*)d_in[6];
    const float* w_ag     = (const float*)d_in[7];
    const float* b_ag     = (const float*)d_in[8];
    const float* w_bp     = (const float*)d_in[9];
    const float* b_bp     = (const float*)d_in[10];
    const float* w_bg     = (const float*)d_in[11];
    const float* b_bg     = (const float*)d_in[12];
    const float* w_g      = (const float*)d_in[13];
    const float* b_g      = (const float*)d_in[14];
    const float* w_z      = (const float*)d_in[15];
    const float* b_z      = (const float*)d_in[16];
    float* out = (float*)d_out;

    const int PROJ_SMEM = 2 * 64 * 136 * 4;                    // 69632
    const int TRI_SMEM  = 2 * 10240 * 4;                       // 81920
    const int FIN_SMEM  = (128 * 72 + 64 * 136 + 640) * 4;     // 74240

    cudaFuncSetAttribute(proj_all_kernel, cudaFuncAttributeMaxDynamicSharedMemorySize, PROJ_SMEM);
    cudaFuncSetAttribute(tri_kernel,      cudaFuncAttributeMaxDynamicSharedMemorySize, TRI_SMEM);
    cudaFuncSetAttribute(final_kernel,    cudaFuncAttributeMaxDynamicSharedMemorySize, FIN_SMEM);

    dim3 pgrid(64, 6);
    prep_w<<<pgrid, 256>>>(w_ap, w_ag, w_bp, w_bg, w_g, w_z);

    proj_all_kernel<<<NPAIR / 64, 256, PROJ_SMEM>>>(
        z, ln_in_w, ln_in_b, b_ap, b_ag, b_bp, b_bg, b_g);

    dim3 tgrid(4, 4, 128);
    tri_kernel<<<tgrid, 256, TRI_SMEM>>>();

    final_kernel<<<NPAIR / 64, 256, FIN_SMEM>>>(ln_out_w, ln_out_b, b_z, out);
}